// round 9
// baseline (speedup 1.0000x reference)
#include <cuda_runtime.h>

#define WS 8
#define BB 64
#define TT 256
#define HH 64
#define NW 248

typedef unsigned long long u64;

__device__ __forceinline__ void fma2(u64 &acc, u64 a, u64 b) {
    asm("fma.rn.f32x2 %0, %1, %2, %0;" : "+l"(acc) : "l"(a), "l"(b));
}
__device__ __forceinline__ void add2(u64 &a, u64 b) {
    asm("add.rn.f32x2 %0, %1, %2;" : "=l"(a) : "l"(a), "l"(b));
}
__device__ __forceinline__ u64 pack2(float a, float b) {
    u64 r; asm("mov.b64 %0, {%1, %2};" : "=l"(r) : "f"(a), "f"(b)); return r;
}
__device__ __forceinline__ float lo_f(u64 v) { return __uint_as_float((unsigned)v); }
__device__ __forceinline__ float hi_f(u64 v) { return __uint_as_float((unsigned)(v >> 32)); }
__device__ __forceinline__ float hsum(u64 v) { return lo_f(v) + hi_f(v); }
__device__ __forceinline__ float tanh_ap(float x) {
    float y; asm("tanh.approx.f32 %0, %1;" : "=f"(y) : "f"(x)); return y;
}
__device__ __forceinline__ u64 shflx(u64 v, int mask) {
    unsigned lo = (unsigned)v, hi = (unsigned)(v >> 32);
    lo = __shfl_xor_sync(0xffffffffu, lo, mask);
    hi = __shfl_xor_sync(0xffffffffu, hi, mask);
    return ((u64)hi << 32) | lo;
}
__device__ __forceinline__ u64 red_sl(u64 v) {   // sum over the 4 sl lanes
    add2(v, shflx(v, 1)); add2(v, shflx(v, 2)); return v;
}

__device__ __forceinline__ float xin_value(const float* trajs, const float* preds,
                                           int w, int s, int f) {
    if (w == 0) return trajs[s * 4 + f];
    if (w < WS) {
        if (s < WS - w) return trajs[(w + s) * 4 + f];
        return (f < 2) ? trajs[(2 * w + s - 1) * 4 + f]
                       : preds[(w + s - WS) * 2 + (f - 2)];
    }
    return (f < 2) ? trajs[(w + s) * 4 + f]
                   : preds[(w + s - WS) * 2 + (f - 2)];
}

__global__ __launch_bounds__(512, 1)
void or_lstm_kernel(const float* __restrict__ traj,
                    const float* __restrict__ Wih0, const float* __restrict__ Whh0,
                    const float* __restrict__ bih0, const float* __restrict__ bhh0,
                    const float* __restrict__ Wih1, const float* __restrict__ Whh1,
                    const float* __restrict__ bih1, const float* __restrict__ bhh1,
                    const float* __restrict__ Wlin, const float* __restrict__ blin,
                    float* __restrict__ out)
{
    const int b    = blockIdx.x;
    const int tid  = threadIdx.x;
    const int lane = tid & 31;
    const int wid  = tid >> 5;       // 16 warps
    const int m    = tid >> 3;       // h-index (0..63)
    const int p    = (tid >> 2) & 1; // gate pair: 0 -> (i,f), 1 -> (g,o)
    const int sl   = tid & 3;        // 16-k slice
    const int L    = tid & 7;        // lane within the 8-thread m-group

    __shared__ __align__(16) float trajs[TT * 4];
    __shared__ __align__(16) float h0s[2][HH], h1s[2][HH];
    __shared__ __align__(16) u64 xgb[WS][2][HH];    // bias0 + Wih0·x, per gate pair
    __shared__ __align__(16) u64 wp_s[2][HH][4];    // Wih0 packed by gate pair
    __shared__ __align__(16) u64 bp_s[2][HH];
    __shared__ float preds[NW * 2];
    __shared__ float predpart[32];
    __shared__ float blin_s[2];

    for (int i = tid; i < TT * 4; i += 512) trajs[i] = traj[b * TT * 4 + i];
    if (tid < 2) blin_s[tid] = blin[tid];
    {   // Wih0 table: (pair, m, feature) -> pack2(gate 2p row, gate 2p+1 row)
        const int pt = tid >> 8, mm = (tid >> 2) & 63, f = tid & 3;
        wp_s[pt][mm][f] = pack2(Wih0[(128 * pt + mm) * 4 + f],
                                Wih0[(128 * pt + 64 + mm) * 4 + f]);
    }
    if (tid < 128) {
        const int pt = tid >> 6, mm = tid & 63;
        bp_s[pt][mm] = pack2(bih0[128 * pt + mm] + bhh0[128 * pt + mm],
                             bih0[128 * pt + 64 + mm] + bhh0[128 * pt + 64 + mm]);
    }

    // ---- recurrent weights -> regs: thread owns gates {2p, 2p+1}, k-slice sl ----
    u64 whh0r[2][8], wih1r[2][8], whh1r[2][8];
    #pragma unroll
    for (int e = 0; e < 2; e++) {
        const int rg = 128 * p + 64 * e + m;
        #pragma unroll
        for (int c = 0; c < 4; c++) {
            const int k0 = 16 * c + 4 * sl;
            ulonglong2 v0 = *(const ulonglong2*)(Whh0 + rg * HH + k0);
            whh0r[e][2 * c] = v0.x; whh0r[e][2 * c + 1] = v0.y;
            ulonglong2 v1 = *(const ulonglong2*)(Wih1 + rg * HH + k0);
            wih1r[e][2 * c] = v1.x; wih1r[e][2 * c + 1] = v1.y;
            ulonglong2 v2 = *(const ulonglong2*)(Whh1 + rg * HH + k0);
            whh1r[e][2 * c] = v2.x; whh1r[e][2 * c + 1] = v2.y;
        }
    }
    const u64 b1 = pack2(bih1[128 * p + m] + bhh1[128 * p + m],
                         bih1[128 * p + 64 + m] + bhh1[128 * p + 64 + m]);
    const int mygate = 2 * p + (sl & 1);
    const float km = (mygate == 2) ? 1.0f : 0.5f;
    const float kb = (mygate == 2) ? 0.0f : 0.5f;
    const float wl = Wlin[p * 64 + m];

    float c0 = 0.f, c1 = 0.f, h0v = 0.f, h1v = 0.f;

    // dot over one 64-vector: 8 fma2 per gate pair
    auto dot16 = [&](u64 acc[2], const float* hbuf, const u64 (&w)[2][8]) {
        #pragma unroll
        for (int c = 0; c < 4; c++) {
            ulonglong2 hv = *(const ulonglong2*)(hbuf + 16 * c + 4 * sl);
            fma2(acc[0], hv.x, w[0][2 * c]); fma2(acc[0], hv.y, w[0][2 * c + 1]);
            fma2(acc[1], hv.x, w[1][2 * c]); fma2(acc[1], hv.y, w[1][2 * c + 1]);
        }
    };
    // A holds reduced gate sums (lo = gate 2p, hi = gate 2p+1); lane does 1 act
    auto cell = [&](u64 A, float &c, bool first) -> float {
        float arg = (sl & 1) ? hi_f(A) : lo_f(A);
        float act = fmaf(km, tanh_ap(km * arg), kb);
        const unsigned base = lane & ~7u;
        float iv = __shfl_sync(0xffffffffu, act, base + 0);
        float fv = __shfl_sync(0xffffffffu, act, base + 1);
        float gv = __shfl_sync(0xffffffffu, act, base + 4);
        float ov = __shfl_sync(0xffffffffu, act, base + 5);
        c = first ? iv * gv : fmaf(fv, c, iv * gv);
        return ov * tanh_ap(c);
    };
    // one warp builds one xgb row (128 u64 entries)
    auto xgb_row = [&](int w, int s) {
        float xf = (lane < 4) ? xin_value(trajs, preds, w, s, lane) : 0.0f;
        u64 px[4];
        #pragma unroll
        for (int f = 0; f < 4; f++) {
            float x = __shfl_sync(0xffffffffu, xf, f);
            px[f] = pack2(x, x);
        }
        #pragma unroll
        for (int r = 0; r < 2; r++) {
            const int mm = lane + 32 * r;
            #pragma unroll
            for (int pt = 0; pt < 2; pt++) {
                u64 a = bp_s[pt][mm];
                #pragma unroll
                for (int f = 0; f < 4; f++) fma2(a, px[f], wp_s[pt][mm][f]);
                xgb[s][pt][mm] = a;
            }
        }
    };

    __syncthreads();                 // trajs + tables staged
    if (wid < 8) xgb_row(0, wid);    // window 0 rows (pure traj)
    __syncthreads();

    for (int w = 0; w < NW; w++) {
        // ===== phase 0: P0(0); side: warp15 builds xgb row 7 (needs pred[w-1])
        {
            u64 A0 = xgb[0][p][m];
            h0v = cell(A0, c0, true);
            if (L == 0) h0s[0][m] = h0v;
            if (w > 0 && wid == 15) xgb_row(w, 7);
        }
        __syncthreads();

        // ===== phase 1: P1(0) + P0(1)
        {
            u64 a1[2] = {0, 0}; dot16(a1, h0s[0], wih1r);
            u64 a0[2] = {0, 0}; dot16(a0, h0s[0], whh0r);
            u64 A1 = red_sl(pack2(hsum(a1[0]), hsum(a1[1]))); add2(A1, b1);
            u64 A0 = red_sl(pack2(hsum(a0[0]), hsum(a0[1]))); add2(A0, xgb[1][p][m]);
            h1v = cell(A1, c1, true);
            if (L == 0) h1s[0][m] = h1v;
            h0v = cell(A0, c0, false);
            if (L == 0) h0s[1][m] = h0v;
        }
        __syncthreads();

        // ===== phases 2..7: P1(s-1) + P0(s)
        #pragma unroll 2
        for (int s = 2; s < WS; s++) {
            const int ps = s & 1, pp = ps ^ 1;
            u64 a1[2] = {0, 0};
            dot16(a1, h0s[pp], wih1r);       // h0(s-1)
            dot16(a1, h1s[ps], whh1r);       // h1(s-2)
            u64 a0[2] = {0, 0};
            dot16(a0, h0s[pp], whh0r);       // h0(s-1)
            u64 A1 = red_sl(pack2(hsum(a1[0]), hsum(a1[1]))); add2(A1, b1);
            u64 A0 = red_sl(pack2(hsum(a0[0]), hsum(a0[1]))); add2(A0, xgb[s][p][m]);
            h1v = cell(A1, c1, false);
            if (L == 0) h1s[pp][m] = h1v;    // h1(s-1)
            h0v = cell(A0, c0, false);
            if (L == 0) h0s[ps][m] = h0v;    // h0(s)
            __syncthreads();
        }

        // ===== phase 8: P1(7) + pred partial (h1v live in all lanes)
        {
            u64 a1[2] = {0, 0};
            dot16(a1, h0s[1], wih1r);        // h0(7)
            dot16(a1, h1s[0], whh1r);        // h1(6)
            u64 A1 = red_sl(pack2(hsum(a1[0]), hsum(a1[1]))); add2(A1, b1);
            h1v = cell(A1, c1, false);
            if (L == 0) h1s[1][m] = h1v;
            float pv = wl * h1v;             // row p of Wlin, this m
            pv += __shfl_xor_sync(0xffffffffu, pv, 8);
            pv += __shfl_xor_sync(0xffffffffu, pv, 16);
            if ((lane & 3) == 0) predpart[wid * 2 + p] = pv;
        }
        __syncthreads();

        // ===== phase F: warps 8..14 build xgb rows 0..6 of w+1; warp15 finalizes pred[w]
        if (wid >= 8 && wid < 15) {
            if (w + 1 < NW) xgb_row(w + 1, wid - 8);
        } else if (wid == 15 && lane < 2) {
            float d = blin_s[lane];
            #pragma unroll
            for (int k = 0; k < 16; k++) d += predpart[k * 2 + lane];
            const float prev = (w == 0) ? trajs[7 * 4 + 2 + lane]
                                        : preds[(w - 1) * 2 + lane];
            const float pr = prev + d;
            preds[w * 2 + lane] = pr;
            out[(b * NW + w) * 2 + lane] = pr;
        }
        __syncthreads();
    }

    // ---- final states: h[2,B,H] then c[2,B,H] (all lanes hold h/c; L==0 writes) ----
    if (L == 0) {
        const int base = BB * NW * 2;
        out[base + 0 * BB * HH + b * HH + m] = h0v;
        out[base + 1 * BB * HH + b * HH + m] = h1v;
        out[base + 2 * BB * HH + b * HH + m] = c0;
        out[base + 3 * BB * HH + b * HH + m] = c1;
    }
}

extern "C" void kernel_launch(void* const* d_in, const int* in_sizes, int n_in,
                              void* d_out, int out_size) {
    const float* traj = (const float*)d_in[0];
    const float* Wih0 = (const float*)d_in[1];
    const float* Whh0 = (const float*)d_in[2];
    const float* bih0 = (const float*)d_in[3];
    const float* bhh0 = (const float*)d_in[4];
    const float* Wih1 = (const float*)d_in[5];
    const float* Whh1 = (const float*)d_in[6];
    const float* bih1 = (const float*)d_in[7];
    const float* bhh1 = (const float*)d_in[8];
    const float* Wlin = (const float*)d_in[9];
    const float* blin = (const float*)d_in[10];

    or_lstm_kernel<<<BB, 512>>>(traj, Wih0, Whh0, bih0, bhh0,
                                Wih1, Whh1, bih1, bhh1,
                                Wlin, blin, (float*)d_out);
}